// round 8
// baseline (speedup 1.0000x reference)
#include <cuda_runtime.h>

#define NL    24
#define TSEQ  256
#define NPOS  96
#define NSEQ  48
#define WARM  64
#define CHK   64
#define NGL   48      // total layers across both stacks

__device__ float g_z[TSEQ * 1536];
__device__ float g_h[TSEQ * 1000];
__device__ float g_hbuf[2][2][NSEQ][TSEQ][16];   // [parity][dir][n2][t][j]
__device__ int   g_flag[NGL][NSEQ][2];

typedef unsigned long long u64;

__device__ __forceinline__ u64 pk2(float lo, float hi) {
    u64 r; asm("mov.b64 %0, {%1, %2};" : "=l"(r) : "f"(lo), "f"(hi)); return r;
}
__device__ __forceinline__ void unpk2(u64 v, float& lo, float& hi) {
    asm("mov.b64 {%0, %1}, %2;" : "=f"(lo), "=f"(hi) : "l"(v));
}
__device__ __forceinline__ u64 fma2_(u64 a, u64 b, u64 c) {
    u64 d; asm("fma.rn.f32x2 %0, %1, %2, %3;" : "=l"(d) : "l"(a), "l"(b), "l"(c)); return d;
}
__device__ __forceinline__ u64 mul2_(u64 a, u64 b) {
    u64 d; asm("mul.rn.f32x2 %0, %1, %2;" : "=l"(d) : "l"(a), "l"(b)); return d;
}
__device__ __forceinline__ u64 add2_(u64 a, u64 b) {
    u64 d; asm("add.rn.f32x2 %0, %1, %2;" : "=l"(d) : "l"(a), "l"(b)); return d;
}
__device__ __forceinline__ float tanhapx_(float x) {
    float r; asm("tanh.approx.f32 %0, %1;" : "=f"(r) : "f"(x)); return r;
}

// gate row r (0..63) lives in xg[t][ (r&31)*2 + (r>>5) ] -> lane's pair (l, l+32) adjacent
__device__ __forceinline__ int remap_(int g) { return ((g & 31) << 1) | (g >> 5); }
// rows: 0-15 i, 16-31 f, 32-47 g, 48-63 o. i/f/o prescaled by 0.5 (sigma-as-tanh).
__device__ __forceinline__ float gscale_(int row) { return (row >= 32 && row < 48) ? 1.f : 0.5f; }

__global__ void reset_flags_kernel() {
    int i = blockIdx.x * 256 + threadIdx.x;
    if (i < NGL * NSEQ * 2) ((int*)g_flag)[i] = 0;
}

// One warp runs ONE chunk of this CTA's direction.
// lane l<16 : rows l (i_l), l+32 (g_l); lane 16+l : rows 16+l (f_l), 48+l (o_l).
__device__ __forceinline__ void lstm_chain(
    const float* __restrict__ xg,    // [T][64] pair-interleaved, prescaled
    const float* __restrict__ whh,   // [64][16] prescaled
    float* __restrict__ s_h,         // [16] per-warp scratch
    float* __restrict__ out_s,       // cin + dir*16, row stride 32
    float* __restrict__ out_g,       // g_hbuf slot, row stride 16
    int chunk, int rev, int lane)
{
    u64 w0[8], w1[8];
    {
        const u64* p0 = (const u64*)(whh + lane * 16);
        const u64* p1 = (const u64*)(whh + (lane + 32) * 16);
#pragma unroll
        for (int k = 0; k < 8; k++) { w0[k] = p0[k]; w1[k] = p1[k]; }
    }
    if (lane < 16) s_h[lane] = 0.f;
    asm volatile("" ::: "memory");

    float c = 0.f;
    const bool lo = lane < 16;
    const float s2 = lo ? 1.f : 0.5f;
    const float a2 = lo ? 0.f : 0.5f;

    const int dt   = rev ? -1 : 1;
    const int warm = rev ? ((chunk < 3) ? WARM : 0) : ((chunk > 0) ? WARM : 0);
    int t = rev ? (chunk * CHK + CHK - 1 + warm) : (chunk * CHK - warm);
    t &= 255;

    float2 xa = *(const float2*)(xg + t * 64 + lane * 2);
    const ulonglong2* hp = (const ulonglong2*)s_h;

#pragma unroll
    for (int phase = 0; phase < 2; phase++) {
        const int iters = phase ? CHK : warm;
#pragma unroll 1
        for (int s = 0; s < iters; s++) {
            u64 hq[8];
#pragma unroll
            for (int k = 0; k < 4; k++) {
                ulonglong2 hv = hp[k];
                hq[2 * k] = hv.x; hq[2 * k + 1] = hv.y;
            }
            u64 p00 = fma2_(w0[0], hq[0], pk2(xa.x, 0.f));
            u64 p01 = mul2_(w0[1], hq[1]);
            u64 p10 = fma2_(w1[0], hq[0], pk2(xa.y, 0.f));
            u64 p11 = mul2_(w1[1], hq[1]);
#pragma unroll
            for (int k = 2; k < 8; k += 2) {
                p00 = fma2_(w0[k], hq[k], p00); p01 = fma2_(w0[k + 1], hq[k + 1], p01);
                p10 = fma2_(w1[k], hq[k], p10); p11 = fma2_(w1[k + 1], hq[k + 1], p11);
            }
            u64 r0 = add2_(p00, p01);
            u64 r1 = add2_(p10, p11);
            float r0l, r0h, r1l, r1h;
            unpk2(r0, r0l, r0h);
            unpk2(r1, r1l, r1h);
            const float v0 = r0l + r0h;
            const float v1 = r1l + r1h;

            const int told = t;
            t = (t + dt) & 255;
            xa = *(const float2*)(xg + t * 64 + lane * 2);

            const float act0 = fmaf(0.5f, tanhapx_(v0), 0.5f);   // sigma(i)/sigma(f)
            const float act1 = fmaf(s2, tanhapx_(v1), a2);       // tanh(g)/sigma(o)

            const float p0 = __shfl_xor_sync(0xffffffffu, act0, 16);
            const float p1 = __shfl_xor_sync(0xffffffffu, act1, 16);
            const float iv = lo ? act0 : p0;
            const float fv = lo ? p0 : act0;
            const float gv = lo ? act1 : p1;
            const float ov = lo ? p1 : act1;
            c = fmaf(fv, c, iv * gv);
            const float hn = ov * tanhapx_(c);
            if (phase && !lo) {
                out_s[told * 32 + (lane - 16)] = hn;
                out_g[told * 16 + (lane - 16)] = hn;
            }
            if (lo) s_h[lane] = hn;
            asm volatile("" ::: "memory");
        }
    }
    __threadfence();   // order hbuf stores before the flag
}

__global__ void __launch_bounds__(256, 1)
lstm_pair_kernel(const float* __restrict__ x,
                 const float* __restrict__ Wih0, const float* __restrict__ Wih1,
                 const float* __restrict__ Whh1, const float* __restrict__ bih1,
                 const float* __restrict__ bhh1,
                 const float* __restrict__ Wih2, const float* __restrict__ Whh2,
                 const float* __restrict__ bih2, const float* __restrict__ bhh2)
{
    extern __shared__ float sm[];
    float* s_xg  = sm;                 // [256][64]  (own dir)
    float* cin   = s_xg + TSEQ * 64;   // [256][32]  (concat input)
    float* s_whh = cin + TSEQ * 32;    // [2][1024]  (double-buffered, own dir)
    float* s_h   = s_whh + 2048;       // [4][16]

    const int bx  = blockIdx.x;
    const int n2  = bx >> 1, dir = bx & 1;
    const int n   = 48 + n2;
    const int tid = threadIdx.x;
    const int wid = tid >> 5, lane = tid & 31;

    // load x into cin col 0
    for (int t = tid; t < TSEQ; t += 256) cin[t * 32] = x[t * NPOS + n];

    // stage whh for gl=0 into buffer 0
    for (int i = tid; i < 1024; i += 256) {
        const int row = i >> 4;
        s_whh[i] = gscale_(row) * Whh1[(size_t)dir * 1024 + i];
    }
    __syncthreads();

    const int gate = tid & 63, quarter = tid >> 6;
    const int gpos = remap_(gate);
    const float gsc = gscale_(gate);
    const int t0 = quarter * 64, t1 = t0 + 64;

    for (int gl = 0; gl < NGL; gl++) {
        const int st = (gl >= NL);
        const int l  = st ? gl - NL : gl;

        // ---- phase A: s_xg[t][gpos] = gsc * (b + Wih . cin_t) ----
        {
            const float* bih = st ? bih2 : bih1;
            const float* bhh = st ? bhh2 : bhh1;
            const int bidx = (l * 2 + dir) * 64 + gate;
            const float b = gsc * (bih[bidx] + bhh[bidx]);
            if (!st && l == 0) {
                const float wsc = gsc * Wih0[dir * 64 + gate];
                for (int t = t0; t < t1; t++)
                    s_xg[t * 64 + gpos] = fmaf(wsc, cin[t * 32], b);
            } else {
                const float* wsrc = st ? (Wih2 + ((size_t)(l * 2 + dir) * 64 + gate) * 32)
                                       : (Wih1 + ((size_t)((l - 1) * 2 + dir) * 64 + gate) * 32);
                const float2* Wv = (const float2*)wsrc;
                u64 w[16];
                const u64 gsc2 = pk2(gsc, gsc);
#pragma unroll
                for (int q = 0; q < 16; q++) { float2 v = Wv[q]; w[q] = mul2_(gsc2, pk2(v.x, v.y)); }
                for (int t = t0; t < t1; t++) {
                    const ulonglong2* xv = (const ulonglong2*)(cin + t * 32);
                    u64 a0 = 0ull, a1 = 0ull, a2v = 0ull, a3 = 0ull;
#pragma unroll
                    for (int q = 0; q < 4; q++) {
                        ulonglong2 xA = xv[2 * q], xB = xv[2 * q + 1];
                        a0  = fma2_(w[4 * q],     xA.x, a0);
                        a1  = fma2_(w[4 * q + 1], xA.y, a1);
                        a2v = fma2_(w[4 * q + 2], xB.x, a2v);
                        a3  = fma2_(w[4 * q + 3], xB.y, a3);
                    }
                    u64 r = add2_(add2_(a0, a1), add2_(a2v, a3));
                    float rl, rh; unpk2(r, rl, rh);
                    s_xg[t * 64 + gpos] = (b + rl) + rh;
                }
            }
        }
        __syncthreads();

        // ---- chains on warps 0-3 (one per SMSP); warps 4-7 stage next whh ----
        if (wid < 4) {
            lstm_chain(s_xg, s_whh + (gl & 1) * 1024, s_h + wid * 16,
                       cin + dir * 16,
                       &g_hbuf[gl & 1][dir][n2][0][0],
                       wid, dir, lane);
        } else if (gl + 1 < NGL) {
            const int gn = gl + 1;
            const float* src = (gn >= NL) ? (Whh2 + (size_t)((gn - NL) * 2 + dir) * 1024)
                                          : (Whh1 + (size_t)(gn * 2 + dir) * 1024);
            float* dst = s_whh + ((gn & 1) * 1024);
            for (int i = tid - 128; i < 1024; i += 128) {
                const int row = i >> 4;
                dst[i] = gscale_(row) * src[i];
            }
        }
        __syncthreads();

        // ---- publish own h, wait for partner ----
        if (tid == 0) {
            __threadfence();
            atomicExch(&g_flag[gl][n2][dir], 1);
            int* pf = &g_flag[gl][n2][dir ^ 1];
            while (atomicAdd(pf, 0) == 0) { __nanosleep(64); }
            __threadfence();
        }
        __syncthreads();

        // ---- load partner half into cin (L2 only, bypass L1) ----
        {
            const float4* src = (const float4*)&g_hbuf[gl & 1][dir ^ 1][n2][0][0];
            // 4096 floats = 1024 float4; 256 threads x 4
#pragma unroll
            for (int q = 0; q < 4; q++) {
                const int i = tid + q * 256;          // float4 index
                const float4 v = __ldcg(src + i);
                const int t = i >> 2, j = (i & 3) * 4;
                float* d = cin + t * 32 + (dir ^ 1) * 16 + j;
                d[0] = v.x; d[1] = v.y; d[2] = v.z; d[3] = v.w;
            }
        }
        __syncthreads();

        // stack-1 end: save x1 (own-dir half) into g_z
        if (gl == NL - 1) {
            for (int i = tid; i < TSEQ * 16; i += 256) {
                const int b_ = i >> 4, j = i & 15;
                g_z[(size_t)b_ * 1536 + n2 * 32 + dir * 16 + j] = cin[b_ * 32 + dir * 16 + j];
            }
        }
    }

    // z = h2 + x1  (own-dir half)
    for (int i = tid; i < TSEQ * 16; i += 256) {
        const int b_ = i >> 4, j = i & 15;
        const size_t idx = (size_t)b_ * 1536 + n2 * 32 + dir * 16 + j;
        g_z[idx] = g_z[idx] + cin[b_ * 32 + dir * 16 + j];
    }
}

// hidden = relu(Z @ W1^T + b1) ; Z:(256,1536), W1:(1000,1536)
__global__ void __launch_bounds__(256)
fc1_kernel(const float* __restrict__ w1, const float* __restrict__ b1)
{
    __shared__ float As[32][33];
    __shared__ float Bs[32][33];
    const int bm = blockIdx.x * 32;
    const int bn = blockIdx.y * 32;
    const int tid = threadIdx.x;
    const int tr = tid >> 5;
    const int tc = tid & 31;
    float acc[4] = {0.f, 0.f, 0.f, 0.f};
    for (int k0 = 0; k0 < 1536; k0 += 32) {
#pragma unroll
        for (int i = 0; i < 4; i++) {
            int r = tr * 4 + i;
            As[r][tc] = g_z[(size_t)(bm + r) * 1536 + k0 + tc];
            int nidx = bn + r;
            Bs[r][tc] = (nidx < 1000) ? w1[(size_t)nidx * 1536 + k0 + tc] : 0.f;
        }
        __syncthreads();
#pragma unroll
        for (int k = 0; k < 32; k++) {
            float bv = Bs[tc][k];
#pragma unroll
            for (int i = 0; i < 4; i++) acc[i] = fmaf(As[tr * 4 + i][k], bv, acc[i]);
        }
        __syncthreads();
    }
    const int nidx = bn + tc;
    if (nidx < 1000) {
        float bb = b1[nidx];
#pragma unroll
        for (int i = 0; i < 4; i++)
            g_h[(size_t)(bm + tr * 4 + i) * 1000 + nidx] = fmaxf(acc[i] + bb, 0.f);
    }
}

// out = hidden @ W2^T + b2 ; W2:(48,1000)
__global__ void __launch_bounds__(256)
fc2_kernel(const float* __restrict__ w2, const float* __restrict__ b2,
           float* __restrict__ out)
{
    __shared__ float sh[1000];
    const int nb = blockIdx.x;
    const int tid = threadIdx.x;
    for (int i = tid; i < 1000; i += 256) sh[i] = g_h[(size_t)nb * 1000 + i];
    __syncthreads();
    const int wid = tid >> 5, lane = tid & 31;
    for (int j = wid; j < 48; j += 8) {
        const float* wr = w2 + j * 1000;
        float acc = 0.f;
        for (int k = lane; k < 1000; k += 32) acc = fmaf(sh[k], wr[k], acc);
#pragma unroll
        for (int off = 16; off; off >>= 1) acc += __shfl_xor_sync(0xffffffffu, acc, off);
        if (lane == 0) out[nb * 48 + j] = acc + b2[j];
    }
}

extern "C" void kernel_launch(void* const* d_in, const int* in_sizes, int n_in,
                              void* d_out, int out_size)
{
    const float* x    = (const float*)d_in[0];
    const float* Wih0 = (const float*)d_in[1];
    const float* Wih1 = (const float*)d_in[2];
    const float* Whh1 = (const float*)d_in[3];
    const float* bih1 = (const float*)d_in[4];
    const float* bhh1 = (const float*)d_in[5];
    const float* Wih2 = (const float*)d_in[6];
    const float* Whh2 = (const float*)d_in[7];
    const float* bih2 = (const float*)d_in[8];
    const float* bhh2 = (const float*)d_in[9];
    const float* w1   = (const float*)d_in[10];
    const float* b1   = (const float*)d_in[11];
    const float* w2   = (const float*)d_in[12];
    const float* b2   = (const float*)d_in[13];
    float* out = (float*)d_out;

    // xg(16384) + cin(8192) + whh(2048) + h(64) floats = 106752 B
    const size_t smem = (size_t)(TSEQ * 64 + TSEQ * 32 + 2048 + 64) * sizeof(float);
    cudaFuncSetAttribute(lstm_pair_kernel, cudaFuncAttributeMaxDynamicSharedMemorySize, (int)smem);

    reset_flags_kernel<<<(NGL * NSEQ * 2 + 255) / 256, 256>>>();
    lstm_pair_kernel<<<2 * NSEQ, 256, smem>>>(x, Wih0, Wih1, Whh1, bih1, bhh1,
                                              Wih2, Whh2, bih2, bhh2);
    fc1_kernel<<<dim3(8, 32), 256>>>(w1, b1);
    fc2_kernel<<<TSEQ, 256>>>(w2, b2, out);
}

// round 10
// speedup vs baseline: 1.4654x; 1.4654x over previous
#include <cuda_runtime.h>

#define NL   24
#define TSEQ 256    // scan length = original batch dim
#define NPOS 96     // positions; only 48..95 survive into stack 2
#define NSEQ 48
#define WARM 32     // chunk warm-up steps (validated: truncation ~0.6^32, below approx noise)
#define CHK  64     // chunk emit length

__device__ float g_z[TSEQ * 1536];
__device__ float g_h[TSEQ * 1000];

typedef unsigned long long u64;

__device__ __forceinline__ u64 pk2(float lo, float hi) {
    u64 r; asm("mov.b64 %0, {%1, %2};" : "=l"(r) : "f"(lo), "f"(hi)); return r;
}
__device__ __forceinline__ void unpk2(u64 v, float& lo, float& hi) {
    asm("mov.b64 {%0, %1}, %2;" : "=f"(lo), "=f"(hi) : "l"(v));
}
__device__ __forceinline__ u64 fma2_(u64 a, u64 b, u64 c) {
    u64 d; asm("fma.rn.f32x2 %0, %1, %2, %3;" : "=l"(d) : "l"(a), "l"(b), "l"(c)); return d;
}
__device__ __forceinline__ u64 mul2_(u64 a, u64 b) {
    u64 d; asm("mul.rn.f32x2 %0, %1, %2;" : "=l"(d) : "l"(a), "l"(b)); return d;
}
__device__ __forceinline__ u64 add2_(u64 a, u64 b) {
    u64 d; asm("add.rn.f32x2 %0, %1, %2;" : "=l"(d) : "l"(a), "l"(b)); return d;
}
__device__ __forceinline__ float tanhapx_(float x) {
    float r; asm("tanh.approx.f32 %0, %1;" : "=f"(r) : "f"(x)); return r;
}

// gate row r (0..63) lives in xg[t][ (r&31)*2 + (r>>5) ]  -> lane's pair (l, l+32) adjacent
__device__ __forceinline__ int remap_(int g) { return ((g & 31) << 1) | (g >> 5); }
// gate rows: 0-15 i, 16-31 f, 32-47 g, 48-63 o.  i/f/o prescaled by 0.5 (sigma-as-tanh).
__device__ __forceinline__ float gscale_(int row) { return (row >= 32 && row < 48) ? 1.f : 0.5f; }

// One warp runs ONE (chunk, dir) of one layer's recurrence.
// lane l<16 : rows l (i_l), l+32 (g_l);  lane 16+l : rows 16+l (f_l), 48+l (o_l).
// Chunk c emits rows [64c, 64c+64); warm-up WARM steps from zero state unless exact end.
__device__ __forceinline__ void lstm_chain(
    const float* __restrict__ xg,    // [T][64] pair-interleaved, prescaled, this dir
    const float* __restrict__ whh,   // [64][16] prescaled, this dir
    float* __restrict__ s_h,         // [16] scratch, private to this warp
    float* __restrict__ outp,        // nxt + dir*16, row stride 32
    int chunk, int rev, int lane)
{
    u64 w0[8], w1[8];
    {
        const u64* p0 = (const u64*)(whh + lane * 16);
        const u64* p1 = (const u64*)(whh + (lane + 32) * 16);
#pragma unroll
        for (int k = 0; k < 8; k++) { w0[k] = p0[k]; w1[k] = p1[k]; }
    }
    if (lane < 16) s_h[lane] = 0.f;
    asm volatile("" ::: "memory");

    float c = 0.f;
    const bool lo = lane < 16;
    const float s2 = lo ? 1.f : 0.5f;   // act1 = tanh(g)  vs  sigma(o)=.5+.5*tanh(.5*o)
    const float a2 = lo ? 0.f : 0.5f;

    const int dt   = rev ? -1 : 1;
    const int warm = rev ? ((chunk < 3) ? WARM : 0) : ((chunk > 0) ? WARM : 0);
    int t = rev ? (chunk * CHK + CHK - 1 + warm) : (chunk * CHK - warm);
    t &= 255;

    float2 xa = *(const float2*)(xg + t * 64 + lane * 2);
    const ulonglong2* hp = (const ulonglong2*)s_h;

#pragma unroll
    for (int phase = 0; phase < 2; phase++) {
        const int iters = phase ? CHK : warm;
#pragma unroll 1
        for (int s = 0; s < iters; s++) {
            u64 hq[8];
#pragma unroll
            for (int k = 0; k < 4; k++) {
                ulonglong2 hv = hp[k];
                hq[2 * k] = hv.x; hq[2 * k + 1] = hv.y;
            }
            u64 p00 = fma2_(w0[0], hq[0], pk2(xa.x, 0.f));
            u64 p01 = mul2_(w0[1], hq[1]);
            u64 p10 = fma2_(w1[0], hq[0], pk2(xa.y, 0.f));
            u64 p11 = mul2_(w1[1], hq[1]);
#pragma unroll
            for (int k = 2; k < 8; k += 2) {
                p00 = fma2_(w0[k], hq[k], p00); p01 = fma2_(w0[k + 1], hq[k + 1], p01);
                p10 = fma2_(w1[k], hq[k], p10); p11 = fma2_(w1[k + 1], hq[k + 1], p11);
            }
            u64 r0 = add2_(p00, p01);
            u64 r1 = add2_(p10, p11);
            float r0l, r0h, r1l, r1h;
            unpk2(r0, r0l, r0h);
            unpk2(r1, r1l, r1h);
            const float v0 = r0l + r0h;   // .5*i_pre  or .5*f_pre
            const float v1 = r1l + r1h;   // g_pre     or .5*o_pre

            const int told = t;
            t = (t + dt) & 255;           // unconditional wrapped prefetch
            xa = *(const float2*)(xg + t * 64 + lane * 2);

            const float act0 = fmaf(0.5f, tanhapx_(v0), 0.5f);   // sigma(i) / sigma(f)
            const float act1 = fmaf(s2, tanhapx_(v1), a2);       // tanh(g)  / sigma(o)

            const float p0 = __shfl_xor_sync(0xffffffffu, act0, 16);
            const float p1 = __shfl_xor_sync(0xffffffffu, act1, 16);
            const float iv = lo ? act0 : p0;
            const float fv = lo ? p0 : act0;
            const float gv = lo ? act1 : p1;
            const float ov = lo ? p1 : act1;
            c = fmaf(fv, c, iv * gv);
            const float hn = ov * tanhapx_(c);
            if (phase && !lo) outp[told * 32 + (lane - 16)] = hn;
            if (lo) s_h[lane] = hn;
            asm volatile("" ::: "memory");
        }
    }
}

__global__ void __launch_bounds__(256, 1)
lstm_kernel(const float* __restrict__ x,
            const float* __restrict__ Wih0, const float* __restrict__ Wih1,
            const float* __restrict__ Whh1, const float* __restrict__ bih1,
            const float* __restrict__ bhh1,
            const float* __restrict__ Wih2, const float* __restrict__ Whh2,
            const float* __restrict__ bih2, const float* __restrict__ bhh2)
{
    extern __shared__ float sm[];
    float* s_xg  = sm;                          // [2][256][64]
    float* bufA  = sm + 2 * TSEQ * 64;          // [256][32]
    float* bufB  = bufA + TSEQ * 32;            // [256][32]
    float* s_whh = bufB + TSEQ * 32;            // [2][64][16]
    float* s_h   = s_whh + 2048;                // [8][16]
    const int n2 = blockIdx.x;
    const int n  = 48 + n2;
    const int tid = threadIdx.x;

    for (int t = tid; t < TSEQ; t += 256) bufA[t * 32] = x[t * NPOS + n];
    __syncthreads();

    float* cur = bufA;
    float* nxt = bufB;

    const int combo = tid & 127, half = tid >> 7;
    const int dirA = combo >> 6, gate = combo & 63;
    const int gpos = remap_(gate);
    const float gsc = gscale_(gate);

    // chain warp mapping (balances 64-step and 96-step warps across SMSPs):
    // wid: 0:(c0,f) 1:(c3,b) 2:(c1,f) 3:(c1,b) 4:(c2,f) 5:(c2,b) 6:(c3,f) 7:(c0,b)
    // SMSP slot sums: 64+96, 64+96, 96+96, 96+96
    const int wid  = tid >> 5, lane = tid & 31;
    const int cdir = wid & 1;
    const int cchk = (wid == 1) ? 3 : (wid == 7) ? 0 : (wid >> 1);

    // ---------------- stack 1 ----------------
    for (int l = 0; l < NL; l++) {
        // stage Whh[l] into smem, prescaled per gate row
        for (int i = tid; i < 2048; i += 256) {
            const int row = (i >> 4) & 63;
            s_whh[i] = gscale_(row) * Whh1[(size_t)l * 2048 + i];
        }
        {   // phase A: xg[dir][t][gpos] = gsc * (bih + bhh + Wih . x_t)
            const int bidx = (l * 2 + dirA) * 64 + gate;
            const float b = gsc * (bih1[bidx] + bhh1[bidx]);
            float* xgd = s_xg + dirA * TSEQ * 64;
            if (l == 0) {
                const float wsc = gsc * Wih0[dirA * 64 + gate];
                for (int t = half * 128; t < half * 128 + 128; t++)
                    xgd[t * 64 + gpos] = fmaf(wsc, cur[t * 32], b);
            } else {
                const float2* Wv = (const float2*)(Wih1 + ((size_t)((l - 1) * 2 + dirA) * 64 + gate) * 32);
                u64 w[16];
                const u64 gsc2 = pk2(gsc, gsc);
#pragma unroll
                for (int q = 0; q < 16; q++) { float2 v = Wv[q]; w[q] = mul2_(gsc2, pk2(v.x, v.y)); }
                for (int t = half * 128; t < half * 128 + 128; t++) {
                    const ulonglong2* xv = (const ulonglong2*)(cur + t * 32);
                    u64 a0 = 0ull, a1 = 0ull, a2v = 0ull, a3 = 0ull;
#pragma unroll
                    for (int q = 0; q < 4; q++) {
                        ulonglong2 xA = xv[2 * q], xB = xv[2 * q + 1];
                        a0  = fma2_(w[4 * q],     xA.x, a0);
                        a1  = fma2_(w[4 * q + 1], xA.y, a1);
                        a2v = fma2_(w[4 * q + 2], xB.x, a2v);
                        a3  = fma2_(w[4 * q + 3], xB.y, a3);
                    }
                    u64 r = add2_(add2_(a0, a1), add2_(a2v, a3));
                    float rl, rh; unpk2(r, rl, rh);
                    xgd[t * 64 + gpos] = (b + rl) + rh;
                }
            }
        }
        __syncthreads();
        lstm_chain(s_xg + cdir * TSEQ * 64, s_whh + cdir * 1024,
                   s_h + wid * 16, nxt + cdir * 16, cchk, cdir, lane);
        __syncthreads();
        float* tmp = cur; cur = nxt; nxt = tmp;
    }

    // Save x1 into g_z (residual added after stack 2).
    for (int i = tid; i < TSEQ * 32; i += 256) {
        const int b_ = i >> 5, c_ = i & 31;
        g_z[(size_t)b_ * 1536 + n2 * 32 + c_] = cur[i];
    }

    // ---------------- stack 2 ----------------
    for (int l = 0; l < NL; l++) {
        for (int i = tid; i < 2048; i += 256) {
            const int row = (i >> 4) & 63;
            s_whh[i] = gscale_(row) * Whh2[(size_t)l * 2048 + i];
        }
        {
            const int bidx = (l * 2 + dirA) * 64 + gate;
            const float b = gsc * (bih2[bidx] + bhh2[bidx]);
            float* xgd = s_xg + dirA * TSEQ * 64;
            const float2* Wv = (const float2*)(Wih2 + ((size_t)(l * 2 + dirA) * 64 + gate) * 32);
            u64 w[16];
            const u64 gsc2 = pk2(gsc, gsc);
#pragma unroll
            for (int q = 0; q < 16; q++) { float2 v = Wv[q]; w[q] = mul2_(gsc2, pk2(v.x, v.y)); }
            for (int t = half * 128; t < half * 128 + 128; t++) {
                const ulonglong2* xv = (const ulonglong2*)(cur + t * 32);
                u64 a0 = 0ull, a1 = 0ull, a2v = 0ull, a3 = 0ull;
#pragma unroll
                for (int q = 0; q < 4; q++) {
                    ulonglong2 xA = xv[2 * q], xB = xv[2 * q + 1];
                    a0  = fma2_(w[4 * q],     xA.x, a0);
                    a1  = fma2_(w[4 * q + 1], xA.y, a1);
                    a2v = fma2_(w[4 * q + 2], xB.x, a2v);
                    a3  = fma2_(w[4 * q + 3], xB.y, a3);
                }
                u64 r = add2_(add2_(a0, a1), add2_(a2v, a3));
                float rl, rh; unpk2(r, rl, rh);
                xgd[t * 64 + gpos] = (b + rl) + rh;
            }
        }
        __syncthreads();
        lstm_chain(s_xg + cdir * TSEQ * 64, s_whh + cdir * 1024,
                   s_h + wid * 16, nxt + cdir * 16, cchk, cdir, lane);
        __syncthreads();
        float* tmp = cur; cur = nxt; nxt = tmp;
    }

    // z = h2 + x1
    for (int i = tid; i < TSEQ * 32; i += 256) {
        const int b_ = i >> 5, c_ = i & 31;
        const size_t idx = (size_t)b_ * 1536 + n2 * 32 + c_;
        g_z[idx] = g_z[idx] + cur[i];
    }
}

// hidden = relu(Z @ W1^T + b1) ; Z:(256,1536), W1:(1000,1536)
__global__ void __launch_bounds__(256)
fc1_kernel(const float* __restrict__ w1, const float* __restrict__ b1)
{
    __shared__ float As[32][33];
    __shared__ float Bs[32][33];
    const int bm = blockIdx.x * 32;
    const int bn = blockIdx.y * 32;
    const int tid = threadIdx.x;
    const int tr = tid >> 5;
    const int tc = tid & 31;
    float acc[4] = {0.f, 0.f, 0.f, 0.f};
    for (int k0 = 0; k0 < 1536; k0 += 32) {
#pragma unroll
        for (int i = 0; i < 4; i++) {
            int r = tr * 4 + i;
            As[r][tc] = g_z[(size_t)(bm + r) * 1536 + k0 + tc];
            int nidx = bn + r;
            Bs[r][tc] = (nidx < 1000) ? w1[(size_t)nidx * 1536 + k0 + tc] : 0.f;
        }
        __syncthreads();
#pragma unroll
        for (int k = 0; k < 32; k++) {
            float bv = Bs[tc][k];
#pragma unroll
            for (int i = 0; i < 4; i++) acc[i] = fmaf(As[tr * 4 + i][k], bv, acc[i]);
        }
        __syncthreads();
    }
    const int nidx = bn + tc;
    if (nidx < 1000) {
        float bb = b1[nidx];
#pragma unroll
        for (int i = 0; i < 4; i++)
            g_h[(size_t)(bm + tr * 4 + i) * 1000 + nidx] = fmaxf(acc[i] + bb, 0.f);
    }
}

// out = hidden @ W2^T + b2 ; W2:(48,1000)
__global__ void __launch_bounds__(256)
fc2_kernel(const float* __restrict__ w2, const float* __restrict__ b2,
           float* __restrict__ out)
{
    __shared__ float sh[1000];
    const int nb = blockIdx.x;
    const int tid = threadIdx.x;
    for (int i = tid; i < 1000; i += 256) sh[i] = g_h[(size_t)nb * 1000 + i];
    __syncthreads();
    const int wid = tid >> 5, lane = tid & 31;
    for (int j = wid; j < 48; j += 8) {
        const float* wr = w2 + j * 1000;
        float acc = 0.f;
        for (int k = lane; k < 1000; k += 32) acc = fmaf(sh[k], wr[k], acc);
#pragma unroll
        for (int off = 16; off; off >>= 1) acc += __shfl_xor_sync(0xffffffffu, acc, off);
        if (lane == 0) out[nb * 48 + j] = acc + b2[j];
    }
}

extern "C" void kernel_launch(void* const* d_in, const int* in_sizes, int n_in,
                              void* d_out, int out_size)
{
    const float* x    = (const float*)d_in[0];
    const float* Wih0 = (const float*)d_in[1];
    const float* Wih1 = (const float*)d_in[2];
    const float* Whh1 = (const float*)d_in[3];
    const float* bih1 = (const float*)d_in[4];
    const float* bhh1 = (const float*)d_in[5];
    const float* Wih2 = (const float*)d_in[6];
    const float* Whh2 = (const float*)d_in[7];
    const float* bih2 = (const float*)d_in[8];
    const float* bhh2 = (const float*)d_in[9];
    const float* w1   = (const float*)d_in[10];
    const float* b1   = (const float*)d_in[11];
    const float* w2   = (const float*)d_in[12];
    const float* b2   = (const float*)d_in[13];
    float* out = (float*)d_out;

    // xg(32768) + bufs(16384) + whh(2048) + h(128) floats = 205312 B
    const size_t smem = (size_t)(2 * TSEQ * 64 + 2 * TSEQ * 32 + 2048 + 128) * sizeof(float);
    cudaFuncSetAttribute(lstm_kernel, cudaFuncAttributeMaxDynamicSharedMemorySize, (int)smem);

    lstm_kernel<<<NSEQ, 256, smem>>>(x, Wih0, Wih1, Whh1, bih1, bhh1,
                                     Wih2, Whh2, bih2, bhh2);
    fc1_kernel<<<dim3(8, 32), 256>>>(w1, b1);
    fc2_kernel<<<TSEQ, 256>>>(w2, b2, out);
}

// round 14
// speedup vs baseline: 1.8867x; 1.2875x over previous
#include <cuda_runtime.h>
#include <cstdint>

#define NL   24
#define NGL  48     // total layers both stacks
#define TSEQ 256
#define NPOS 96
#define NSEQ 48
#define WARM 32
#define CHK  64

__device__ float g_z[TSEQ * 1536];
__device__ float g_h[TSEQ * 1000];

typedef unsigned long long u64;

__device__ __forceinline__ u64 pk2(float lo, float hi) {
    u64 r; asm("mov.b64 %0, {%1, %2};" : "=l"(r) : "f"(lo), "f"(hi)); return r;
}
__device__ __forceinline__ void unpk2(u64 v, float& lo, float& hi) {
    asm("mov.b64 {%0, %1}, %2;" : "=f"(lo), "=f"(hi) : "l"(v));
}
__device__ __forceinline__ u64 fma2_(u64 a, u64 b, u64 c) {
    u64 d; asm("fma.rn.f32x2 %0, %1, %2, %3;" : "=l"(d) : "l"(a), "l"(b), "l"(c)); return d;
}
__device__ __forceinline__ u64 mul2_(u64 a, u64 b) {
    u64 d; asm("mul.rn.f32x2 %0, %1, %2;" : "=l"(d) : "l"(a), "l"(b)); return d;
}
__device__ __forceinline__ u64 add2_(u64 a, u64 b) {
    u64 d; asm("add.rn.f32x2 %0, %1, %2;" : "=l"(d) : "l"(a), "l"(b)); return d;
}
__device__ __forceinline__ float tanhapx_(float x) {
    float r; asm("tanh.approx.f32 %0, %1;" : "=f"(r) : "f"(x)); return r;
}
__device__ __forceinline__ uint32_t smem_u32(const void* p) {
    uint32_t a;
    asm("{ .reg .u64 t; cvta.to.shared.u64 t, %1; cvt.u32.u64 %0, t; }" : "=r"(a) : "l"(p));
    return a;
}
__device__ __forceinline__ uint32_t mapa_(uint32_t a, uint32_t rank) {
    uint32_t r; asm("mapa.shared::cluster.u32 %0, %1, %2;" : "=r"(r) : "r"(a), "r"(rank));
    return r;
}
__device__ __forceinline__ float4 ldsc4_(uint32_t a) {
    float4 v;
    asm volatile("ld.shared::cluster.v4.f32 {%0,%1,%2,%3}, [%4];"
                 : "=f"(v.x), "=f"(v.y), "=f"(v.z), "=f"(v.w) : "r"(a));
    return v;
}
#define CLUSTER_SYNC() do { \
    asm volatile("barrier.cluster.arrive.aligned;" ::: "memory"); \
    asm volatile("barrier.cluster.wait.aligned;" ::: "memory"); } while (0)

// gate row r (0..63) lives in xg[t][ (r&31)*2 + (r>>5) ] -> lane's pair (l, l+32) adjacent
__device__ __forceinline__ int remap_(int g) { return ((g & 31) << 1) | (g >> 5); }
// rows: 0-15 i, 16-31 f, 32-47 g, 48-63 o. i/f/o prescaled by 0.5 (sigma-as-tanh).
__device__ __forceinline__ float gscale_(int row) { return (row >= 32 && row < 48) ? 1.f : 0.5f; }

// One warp runs ONE (chunk, dir). lane l<16: rows l(i), l+32(g); lane 16+l: 16+l(f), 48+l(o).
__device__ __forceinline__ void lstm_chain(
    const float* __restrict__ xg,    // [T][64] pair-interleaved, prescaled, this dir
    const float* __restrict__ whh,   // [64][16] prescaled, this dir
    float* __restrict__ s_h,         // [16] scratch, private to this warp
    float* __restrict__ outp,        // nxt + dir*16, row stride 32
    int chunk, int rev, int lane)
{
    u64 w0[8], w1[8];
    {
        const u64* p0 = (const u64*)(whh + lane * 16);
        const u64* p1 = (const u64*)(whh + (lane + 32) * 16);
#pragma unroll
        for (int k = 0; k < 8; k++) { w0[k] = p0[k]; w1[k] = p1[k]; }
    }
    if (lane < 16) s_h[lane] = 0.f;
    asm volatile("" ::: "memory");

    float c = 0.f;
    const bool lo = lane < 16;
    const float s2 = lo ? 1.f : 0.5f;
    const float a2 = lo ? 0.f : 0.5f;

    const int dt   = rev ? -1 : 1;
    const int warm = rev ? ((chunk < 3) ? WARM : 0) : ((chunk > 0) ? WARM : 0);
    int t = rev ? (chunk * CHK + CHK - 1 + warm) : (chunk * CHK - warm);
    t &= 255;

    float2 xa = *(const float2*)(xg + t * 64 + lane * 2);
    const ulonglong2* hp = (const ulonglong2*)s_h;

#pragma unroll
    for (int phase = 0; phase < 2; phase++) {
        const int iters = phase ? CHK : warm;
#pragma unroll 1
        for (int s = 0; s < iters; s++) {
            u64 hq[8];
#pragma unroll
            for (int k = 0; k < 4; k++) {
                ulonglong2 hv = hp[k];
                hq[2 * k] = hv.x; hq[2 * k + 1] = hv.y;
            }
            u64 p00 = fma2_(w0[0], hq[0], pk2(xa.x, 0.f));
            u64 p01 = mul2_(w0[1], hq[1]);
            u64 p10 = fma2_(w1[0], hq[0], pk2(xa.y, 0.f));
            u64 p11 = mul2_(w1[1], hq[1]);
#pragma unroll
            for (int k = 2; k < 8; k += 2) {
                p00 = fma2_(w0[k], hq[k], p00); p01 = fma2_(w0[k + 1], hq[k + 1], p01);
                p10 = fma2_(w1[k], hq[k], p10); p11 = fma2_(w1[k + 1], hq[k + 1], p11);
            }
            u64 r0 = add2_(p00, p01);
            u64 r1 = add2_(p10, p11);
            float r0l, r0h, r1l, r1h;
            unpk2(r0, r0l, r0h);
            unpk2(r1, r1l, r1h);
            const float v0 = r0l + r0h;
            const float v1 = r1l + r1h;

            const int told = t;
            t = (t + dt) & 255;
            xa = *(const float2*)(xg + t * 64 + lane * 2);

            const float act0 = fmaf(0.5f, tanhapx_(v0), 0.5f);   // sigma(i)/sigma(f)
            const float act1 = fmaf(s2, tanhapx_(v1), a2);       // tanh(g)/sigma(o)

            const float p0 = __shfl_xor_sync(0xffffffffu, act0, 16);
            const float p1 = __shfl_xor_sync(0xffffffffu, act1, 16);
            const float iv = lo ? act0 : p0;
            const float fv = lo ? p0 : act0;
            const float gv = lo ? act1 : p1;
            const float ov = lo ? p1 : act1;
            c = fmaf(fv, c, iv * gv);
            const float hn = ov * tanhapx_(c);
            if (phase && !lo) outp[told * 32 + (lane - 16)] = hn;
            if (lo) s_h[lane] = hn;
            asm volatile("" ::: "memory");
        }
    }
}

// Cluster of 2 CTAs per position. crank0: chunks {0,1} (needs t in [0,160));
// crank1: chunks {2,3} (needs t in [96,256)). 4KB boundary-row DSMEM exchange per layer.
__global__ void __launch_bounds__(256, 1) __cluster_dims__(2, 1, 1)
lstm_kernel(const float* __restrict__ x,
            const float* __restrict__ Wih0, const float* __restrict__ Wih1,
            const float* __restrict__ Whh1, const float* __restrict__ bih1,
            const float* __restrict__ bhh1,
            const float* __restrict__ Wih2, const float* __restrict__ Whh2,
            const float* __restrict__ bih2, const float* __restrict__ bhh2)
{
    extern __shared__ float sm[];
    float* s_xg  = sm;                       // [2][256][64]  32768
    float* bufA  = sm + 2 * TSEQ * 64;       // [256][32]
    float* bufB  = bufA + TSEQ * 32;         // [256][32]
    float* s_whh = bufB + TSEQ * 32;         // [2][2][64][16] double-buffered, both dirs
    float* s_h   = s_whh + 4096;             // [4][16]

    const int bx = blockIdx.x;
    const int n2 = bx >> 1, crank = bx & 1;
    const int n  = 48 + n2;
    const int tid = threadIdx.x;
    const int wid = tid >> 5, lane = tid & 31;

    for (int t = tid; t < TSEQ; t += 256) bufA[t * 32] = x[t * NPOS + n];
    for (int i = tid; i < 2048; i += 256) {            // stage whh for gl=0
        const int row = (i >> 4) & 63;
        s_whh[i] = gscale_(row) * Whh1[i];
    }
    __syncthreads();

    float* cur = bufA;
    float* nxt = bufB;

    const int combo = tid & 127, half = tid >> 7;
    const int dirA = combo >> 6, gate = combo & 63;
    const int gpos = remap_(gate);
    const float gsc = gscale_(gate);
    const int myt0 = crank * 96 + half * 80;           // phase-A t subrange (80 each)

    for (int gl = 0; gl < NGL; gl++) {
        const int st = (gl >= NL);
        const int l  = st ? gl - NL : gl;

        // ---- phase A over own t-range ----
        {
            const float* bih = st ? bih2 : bih1;
            const float* bhh = st ? bhh2 : bhh1;
            const int bidx = (l * 2 + dirA) * 64 + gate;
            const float b = gsc * (bih[bidx] + bhh[bidx]);
            float* xgd = s_xg + dirA * TSEQ * 64;
            if (!st && l == 0) {
                const float wsc = gsc * Wih0[dirA * 64 + gate];
                for (int t = myt0; t < myt0 + 80; t++)
                    xgd[t * 64 + gpos] = fmaf(wsc, cur[t * 32], b);
            } else {
                const float* wsrc = st ? (Wih2 + ((size_t)(l * 2 + dirA) * 64 + gate) * 32)
                                       : (Wih1 + ((size_t)((l - 1) * 2 + dirA) * 64 + gate) * 32);
                const float2* Wv = (const float2*)wsrc;
                u64 w[16];
                const u64 gsc2 = pk2(gsc, gsc);
#pragma unroll
                for (int q = 0; q < 16; q++) { float2 v = Wv[q]; w[q] = mul2_(gsc2, pk2(v.x, v.y)); }
                for (int t = myt0; t < myt0 + 80; t++) {
                    const ulonglong2* xv = (const ulonglong2*)(cur + t * 32);
                    u64 a0 = 0ull, a1 = 0ull, a2v = 0ull, a3 = 0ull;
#pragma unroll
                    for (int q = 0; q < 4; q++) {
                        ulonglong2 xA = xv[2 * q], xB = xv[2 * q + 1];
                        a0  = fma2_(w[4 * q],     xA.x, a0);
                        a1  = fma2_(w[4 * q + 1], xA.y, a1);
                        a2v = fma2_(w[4 * q + 2], xB.x, a2v);
                        a3  = fma2_(w[4 * q + 3], xB.y, a3);
                    }
                    u64 r = add2_(add2_(a0, a1), add2_(a2v, a3));
                    float rl, rh; unpk2(r, rl, rh);
                    xgd[t * 64 + gpos] = (b + rl) + rh;
                }
            }
        }
        __syncthreads();

        // ---- chains on warps 0-3 (one per SMSP, <=96 steps); warps 4-7 stage next whh ----
        if (wid < 4) {
            const int cchk = crank * 2 + (wid >> 1);
            const int cdir = wid & 1;
            lstm_chain(s_xg + cdir * TSEQ * 64,
                       s_whh + (gl & 1) * 2048 + cdir * 1024,
                       s_h + wid * 16, nxt + cdir * 16, cchk, cdir, lane);
        } else if (gl + 1 < NGL) {
            const int gn = gl + 1;
            const float* src = (gn >= NL) ? (Whh2 + (size_t)(gn - NL) * 2048)
                                          : (Whh1 + (size_t)gn * 2048);
            float* dst = s_whh + (gn & 1) * 2048;
            for (int i = tid - 128; i < 2048; i += 128) {
                const int row = (i >> 4) & 63;
                dst[i] = gscale_(row) * src[i];
            }
        }
        CLUSTER_SYNC();   // block+cluster barrier: peer's nxt writes now visible

        // ---- DSMEM: pull 32 peer boundary rows into own nxt ----
        {
            const int lo = crank ? 96 : 128;               // rows [lo, lo+32)
            const uint32_t myaddr = smem_u32(nxt) + (uint32_t)lo * 128 + (uint32_t)tid * 16;
            const float4 v = ldsc4_(mapa_(myaddr, crank ^ 1));
            *(float4*)((char*)nxt + lo * 128 + tid * 16) = v;
        }
        __syncthreads();

        float* tmp = cur; cur = nxt; nxt = tmp;

        if (gl == NL - 1) {       // save x1 (own rows) into g_z
            for (int i = tid; i < 128 * 32; i += 256) {
                const int b_ = crank * 128 + (i >> 5), c_ = i & 31;
                g_z[(size_t)b_ * 1536 + n2 * 32 + c_] = cur[b_ * 32 + c_];
            }
        }
    }

    // z = h2 + x1 (own rows)
    for (int i = tid; i < 128 * 32; i += 256) {
        const int b_ = crank * 128 + (i >> 5), c_ = i & 31;
        const size_t idx = (size_t)b_ * 1536 + n2 * 32 + c_;
        g_z[idx] = g_z[idx] + cur[b_ * 32 + c_];
    }
}

// hidden = relu(Z @ W1^T + b1) ; Z:(256,1536), W1:(1000,1536)
__global__ void __launch_bounds__(256)
fc1_kernel(const float* __restrict__ w1, const float* __restrict__ b1)
{
    __shared__ float As[32][33];
    __shared__ float Bs[32][33];
    const int bm = blockIdx.x * 32;
    const int bn = blockIdx.y * 32;
    const int tid = threadIdx.x;
    const int tr = tid >> 5;
    const int tc = tid & 31;
    float acc[4] = {0.f, 0.f, 0.f, 0.f};
    for (int k0 = 0; k0 < 1536; k0 += 32) {
#pragma unroll
        for (int i = 0; i < 4; i++) {
            int r = tr * 4 + i;
            As[r][tc] = g_z[(size_t)(bm + r) * 1536 + k0 + tc];
            int nidx = bn + r;
            Bs[r][tc] = (nidx < 1000) ? w1[(size_t)nidx * 1536 + k0 + tc] : 0.f;
        }
        __syncthreads();
#pragma unroll
        for (int k = 0; k < 32; k++) {
            float bv = Bs[tc][k];
#pragma unroll
            for (int i = 0; i < 4; i++) acc[i] = fmaf(As[tr * 4 + i][k], bv, acc[i]);
        }
        __syncthreads();
    }
    const int nidx = bn + tc;
    if (nidx < 1000) {
        float bb = b1[nidx];
#pragma unroll
        for (int i = 0; i < 4; i++)
            g_h[(size_t)(bm + tr * 4 + i) * 1000 + nidx] = fmaxf(acc[i] + bb, 0.f);
    }
}

// out = hidden @ W2^T + b2 ; W2:(48,1000)
__global__ void __launch_bounds__(256)
fc2_kernel(const float* __restrict__ w2, const float* __restrict__ b2,
           float* __restrict__ out)
{
    __shared__ float sh[1000];
    const int nb = blockIdx.x;
    const int tid = threadIdx.x;
    for (int i = tid; i < 1000; i += 256) sh[i] = g_h[(size_t)nb * 1000 + i];
    __syncthreads();
    const int wid = tid >> 5, lane = tid & 31;
    for (int j = wid; j < 48; j += 8) {
        const float* wr = w2 + j * 1000;
        float acc = 0.f;
        for (int k = lane; k < 1000; k += 32) acc = fmaf(sh[k], wr[k], acc);
#pragma unroll
        for (int off = 16; off; off >>= 1) acc += __shfl_xor_sync(0xffffffffu, acc, off);
        if (lane == 0) out[nb * 48 + j] = acc + b2[j];
    }
}

extern "C" void kernel_launch(void* const* d_in, const int* in_sizes, int n_in,
                              void* d_out, int out_size)
{
    const float* x    = (const float*)d_in[0];
    const float* Wih0 = (const float*)d_in[1];
    const float* Wih1 = (const float*)d_in[2];
    const float* Whh1 = (const float*)d_in[3];
    const float* bih1 = (const float*)d_in[4];
    const float* bhh1 = (const float*)d_in[5];
    const float* Wih2 = (const float*)d_in[6];
    const float* Whh2 = (const float*)d_in[7];
    const float* bih2 = (const float*)d_in[8];
    const float* bhh2 = (const float*)d_in[9];
    const float* w1   = (const float*)d_in[10];
    const float* b1   = (const float*)d_in[11];
    const float* w2   = (const float*)d_in[12];
    const float* b2   = (const float*)d_in[13];
    float* out = (float*)d_out;

    // xg(32768) + bufs(16384) + whh(4096) + h(64) floats = 213,248 B
    const size_t smem = (size_t)(2 * TSEQ * 64 + 2 * TSEQ * 32 + 4096 + 64) * sizeof(float);
    cudaFuncSetAttribute(lstm_kernel, cudaFuncAttributeMaxDynamicSharedMemorySize, (int)smem);

    lstm_kernel<<<2 * NSEQ, 256, smem>>>(x, Wih0, Wih1, Whh1, bih1, bhh1,
                                         Wih2, Whh2, bih2, bhh2);
    fc1_kernel<<<dim3(8, 32), 256>>>(w1, b1);
    fc2_kernel<<<TSEQ, 256>>>(w2, b2, out);
}

// round 16
// speedup vs baseline: 2.0122x; 1.0665x over previous
#include <cuda_runtime.h>
#include <cstdint>

#define NL   24
#define NGL  48
#define TSEQ 256
#define NPOS 96
#define NSEQ 48
#define WARM 32
#define CHK  64
#define XGW  162          // local xg window rows (160 + 2 guard)
#define WIHP 34           // padded Wih row stride

__device__ float g_z[TSEQ * 1536];
__device__ float g_h[TSEQ * 1000];

typedef unsigned long long u64;

__device__ __forceinline__ u64 pk2(float lo, float hi) {
    u64 r; asm("mov.b64 %0, {%1, %2};" : "=l"(r) : "f"(lo), "f"(hi)); return r;
}
__device__ __forceinline__ void unpk2(u64 v, float& lo, float& hi) {
    asm("mov.b64 {%0, %1}, %2;" : "=f"(lo), "=f"(hi) : "l"(v));
}
__device__ __forceinline__ u64 fma2_(u64 a, u64 b, u64 c) {
    u64 d; asm("fma.rn.f32x2 %0, %1, %2, %3;" : "=l"(d) : "l"(a), "l"(b), "l"(c)); return d;
}
__device__ __forceinline__ u64 mul2_(u64 a, u64 b) {
    u64 d; asm("mul.rn.f32x2 %0, %1, %2;" : "=l"(d) : "l"(a), "l"(b)); return d;
}
__device__ __forceinline__ u64 add2_(u64 a, u64 b) {
    u64 d; asm("add.rn.f32x2 %0, %1, %2;" : "=l"(d) : "l"(a), "l"(b)); return d;
}
__device__ __forceinline__ float tanhapx_(float x) {
    float r; asm("tanh.approx.f32 %0, %1;" : "=f"(r) : "f"(x)); return r;
}
__device__ __forceinline__ uint32_t smem_u32(const void* p) {
    uint32_t a;
    asm("{ .reg .u64 t; cvta.to.shared.u64 t, %1; cvt.u32.u64 %0, t; }" : "=r"(a) : "l"(p));
    return a;
}
__device__ __forceinline__ uint32_t mapa_(uint32_t a, uint32_t rank) {
    uint32_t r; asm("mapa.shared::cluster.u32 %0, %1, %2;" : "=r"(r) : "r"(a), "r"(rank));
    return r;
}
__device__ __forceinline__ float4 ldsc4_(uint32_t a) {
    float4 v;
    asm volatile("ld.shared::cluster.v4.f32 {%0,%1,%2,%3}, [%4];"
                 : "=f"(v.x), "=f"(v.y), "=f"(v.z), "=f"(v.w) : "r"(a));
    return v;
}
#define CLUSTER_SYNC() do { \
    asm volatile("barrier.cluster.arrive.aligned;" ::: "memory"); \
    asm volatile("barrier.cluster.wait.aligned;" ::: "memory"); } while (0)

__device__ __forceinline__ int remap_(int g) { return ((g & 31) << 1) | (g >> 5); }
// rows 0-15 i, 16-31 f, 32-47 g, 48-63 o. i/f/o prescaled by 0.5 (sigma-as-tanh).
__device__ __forceinline__ float gscale_(int row) { return (row >= 32 && row < 48) ? 1.f : 0.5f; }

// One warp, one (chunk, dir). lane l<16: rows l(i), l+32(g); lane 16+l: 16+l(f), 48+l(o).
__device__ __forceinline__ void lstm_chain(
    const float* __restrict__ xg,    // local window [XGW][64], this dir (row lt = t - tbase + 1)
    const float* __restrict__ whh,   // [64][16] prescaled, this dir
    float* __restrict__ s_h,         // [16] per-warp scratch
    float* __restrict__ nxt,         // [256][32] absolute
    int tbase, int chunk, int rev, int lane)
{
    u64 w0[8], w1[8];
    {
        const u64* p0 = (const u64*)(whh + lane * 16);
        const u64* p1 = (const u64*)(whh + (lane + 32) * 16);
#pragma unroll
        for (int k = 0; k < 8; k++) { w0[k] = p0[k]; w1[k] = p1[k]; }
    }
    if (lane < 16) s_h[lane] = 0.f;
    asm volatile("" ::: "memory");

    float c = 0.f;
    const bool lo = lane < 16;
    const float s2 = lo ? 1.f : 0.5f;
    const float a2 = lo ? 0.f : 0.5f;

    const int dt   = rev ? -1 : 1;
    const int warm = rev ? ((chunk < 3) ? WARM : 0) : ((chunk > 0) ? WARM : 0);
    const int t0   = rev ? (chunk * CHK + CHK - 1 + warm) : (chunk * CHK - warm);

    const float* xp = xg + (t0 - tbase + 1) * 64 + lane * 2;
    float*       op = nxt + t0 * 32 + rev * 16 + (lane & 15);   // dir offset (fixed)
    const int xstep = dt * 64, ostep = dt * 32;

    float2 xa = *(const float2*)xp; xp += xstep;
    const ulonglong2* hp = (const ulonglong2*)s_h;

#pragma unroll
    for (int phase = 0; phase < 2; phase++) {
        const int iters = phase ? CHK : warm;
#pragma unroll 2
        for (int s = 0; s < iters; s++) {
            u64 hq[8];
#pragma unroll
            for (int k = 0; k < 4; k++) {
                ulonglong2 hv = hp[k];
                hq[2 * k] = hv.x; hq[2 * k + 1] = hv.y;
            }
            // 4-accumulator depth-2 trees per gate row
            u64 q0 = fma2_(w0[0], hq[0], pk2(xa.x, 0.f));
            u64 q1 = mul2_(w0[1], hq[1]);
            u64 q2 = mul2_(w0[2], hq[2]);
            u64 q3 = mul2_(w0[3], hq[3]);
            u64 r0v = fma2_(w1[0], hq[0], pk2(xa.y, 0.f));
            u64 r1v = mul2_(w1[1], hq[1]);
            u64 r2v = mul2_(w1[2], hq[2]);
            u64 r3v = mul2_(w1[3], hq[3]);
            q0 = fma2_(w0[4], hq[4], q0);  q1 = fma2_(w0[5], hq[5], q1);
            q2 = fma2_(w0[6], hq[6], q2);  q3 = fma2_(w0[7], hq[7], q3);
            r0v = fma2_(w1[4], hq[4], r0v); r1v = fma2_(w1[5], hq[5], r1v);
            r2v = fma2_(w1[6], hq[6], r2v); r3v = fma2_(w1[7], hq[7], r3v);
            u64 sa = add2_(add2_(q0, q1), add2_(q2, q3));
            u64 sb = add2_(add2_(r0v, r1v), add2_(r2v, r3v));
            float al, ah, bl, bh;
            unpk2(sa, al, ah); unpk2(sb, bl, bh);
            const float v0 = al + ah;   // .5*i_pre or .5*f_pre
            const float v1 = bl + bh;   // g_pre    or .5*o_pre

            xa = *(const float2*)xp; xp += xstep;   // guard rows absorb overflow

            const float act0 = fmaf(0.5f, tanhapx_(v0), 0.5f);   // sigma(i)/sigma(f)
            const float act1 = fmaf(s2, tanhapx_(v1), a2);       // tanh(g)/sigma(o)

            const float p0 = __shfl_xor_sync(0xffffffffu, act0, 16);
            const float p1 = __shfl_xor_sync(0xffffffffu, act1, 16);
            const float iv = lo ? act0 : p0;
            const float fv = lo ? p0 : act0;
            const float gv = lo ? act1 : p1;
            const float ov = lo ? p1 : act1;
            c = fmaf(fv, c, iv * gv);
            const float hn = ov * tanhapx_(c);
            if (phase && !lo) *op = hn;
            op += ostep;
            if (lo) s_h[lane] = hn;
            asm volatile("" ::: "memory");
        }
    }
}

// 2-CTA cluster per position. crank0: chunks {0,1} (t in [0,160)); crank1: chunks {2,3} ([96,256)).
__global__ void __launch_bounds__(256, 1) __cluster_dims__(2, 1, 1)
lstm_kernel(const float* __restrict__ x,
            const float* __restrict__ Wih0, const float* __restrict__ Wih1,
            const float* __restrict__ Whh1, const float* __restrict__ bih1,
            const float* __restrict__ bhh1,
            const float* __restrict__ Wih2, const float* __restrict__ Whh2,
            const float* __restrict__ bih2, const float* __restrict__ bhh2)
{
    extern __shared__ float sm[];
    float* s_xg  = sm;                        // [2][XGW][64]          20736
    float* bufA  = s_xg + 2 * XGW * 64;       // [256][32]             8192
    float* bufB  = bufA + TSEQ * 32;          // [256][32]             8192
    float* s_whh = bufB + TSEQ * 32;          // [2][2][64][16]        4096
    float* s_wih = s_whh + 4096;              // [2][128][WIHP]        8704
    float* s_h   = s_wih + 2 * 128 * WIHP;    // [4][16]               64

    const int bx = blockIdx.x;
    const int n2 = bx >> 1, crank = bx & 1;
    const int n  = 48 + n2;
    const int tid = threadIdx.x;
    const int wid = tid >> 5, lane = tid & 31;
    const int tbase = crank * 96;

    for (int t = tid; t < TSEQ; t += 256) bufA[t * 32] = x[t * NPOS + n];
    for (int i = tid; i < 2048; i += 256) {            // whh for gl=0 -> buffer 0
        const int row = (i >> 4) & 63;
        s_whh[i] = gscale_(row) * Whh1[i];
    }
    __syncthreads();

    float* cur = bufA;
    float* nxt = bufB;

    const int combo = tid & 127, half = tid >> 7;
    const int dirA = combo >> 6, gate = combo & 63;
    const int gpos = remap_(gate);
    const float gsc = gscale_(gate);
    const int lr0 = half * 80;                          // local row range [lr0, lr0+80)

    for (int gl = 0; gl < NGL; gl++) {
        const int st = (gl >= NL);
        const int l  = st ? gl - NL : gl;

        // ---- phase A: xg[dirA][lr+1][gpos] over own 80 local rows ----
        {
            const float* bih = st ? bih2 : bih1;
            const float* bhh = st ? bhh2 : bhh1;
            const int bidx = (l * 2 + dirA) * 64 + gate;
            const float b = gsc * (bih[bidx] + bhh[bidx]);
            float* xgd = s_xg + dirA * XGW * 64;
            if (gl == 0) {
                const float wsc = gsc * Wih0[dirA * 64 + gate];
                for (int lr = lr0; lr < lr0 + 80; lr++)
                    xgd[(lr + 1) * 64 + gpos] = fmaf(wsc, cur[(tbase + lr) * 32], b);
            } else {
                const float* wrow = s_wih + (gl & 1) * 128 * WIHP + (dirA * 64 + gate) * WIHP;
                u64 w[16];
#pragma unroll
                for (int q = 0; q < 16; q++) w[q] = *(const u64*)(wrow + 2 * q);  // prescaled
                for (int lr = lr0; lr < lr0 + 80; lr++) {
                    const ulonglong2* xv = (const ulonglong2*)(cur + (tbase + lr) * 32);
                    u64 a0 = 0ull, a1 = 0ull, a2v = 0ull, a3 = 0ull;
#pragma unroll
                    for (int q = 0; q < 4; q++) {
                        ulonglong2 xA = xv[2 * q], xB = xv[2 * q + 1];
                        a0  = fma2_(w[4 * q],     xA.x, a0);
                        a1  = fma2_(w[4 * q + 1], xA.y, a1);
                        a2v = fma2_(w[4 * q + 2], xB.x, a2v);
                        a3  = fma2_(w[4 * q + 3], xB.y, a3);
                    }
                    u64 r = add2_(add2_(a0, a1), add2_(a2v, a3));
                    float rl, rh; unpk2(r, rl, rh);
                    xgd[(lr + 1) * 64 + gpos] = (b + rl) + rh;
                }
            }
        }
        __syncthreads();

        // ---- warps 0-3: chains; warps 4-7: stage next layer's whh + wih ----
        if (wid < 4) {
            const int cchk = crank * 2 + (wid >> 1);
            const int cdir = wid & 1;
            lstm_chain(s_xg + cdir * XGW * 64,
                       s_whh + (gl & 1) * 2048 + cdir * 1024,
                       s_h + wid * 16, nxt, tbase, cchk, cdir, lane);
        } else if (gl + 1 < NGL) {
            const int gn = gl + 1;
            {   // whh
                const float* src = (gn >= NL) ? (Whh2 + (size_t)(gn - NL) * 2048)
                                              : (Whh1 + (size_t)gn * 2048);
                float* dst = s_whh + (gn & 1) * 2048;
                for (int i = tid - 128; i < 2048; i += 128) {
                    const int row = (i >> 4) & 63;
                    dst[i] = gscale_(row) * src[i];
                }
            }
            {   // wih (prescaled, padded)
                const float* src = (gn >= NL) ? (Wih2 + (size_t)(gn - NL) * 4096)
                                              : (Wih1 + (size_t)(gn - 1) * 4096);
                float* dst = s_wih + (gn & 1) * 128 * WIHP;
                for (int i = tid - 128; i < 4096; i += 128) {
                    const int g_ = (i >> 5) & 63;
                    dst[(i >> 5) * WIHP + (i & 31)] = gscale_(g_) * src[i];
                }
            }
        }
        CLUSTER_SYNC();   // full cluster barrier: peer's nxt writes visible

        // ---- DSMEM: pull 32 peer boundary rows into own nxt ----
        {
            const int lo = crank ? 96 : 128;               // rows [lo, lo+32)
            const uint32_t myaddr = smem_u32(nxt) + (uint32_t)lo * 128 + (uint32_t)tid * 16;
            const float4 v = ldsc4_(mapa_(myaddr, crank ^ 1));
            *(float4*)((char*)nxt + lo * 128 + tid * 16) = v;
        }
        __syncthreads();

        float* tmp = cur; cur = nxt; nxt = tmp;

        if (gl == NL - 1) {       // save x1 (own rows) into g_z
            for (int i = tid; i < 128 * 32; i += 256) {
                const int b_ = crank * 128 + (i >> 5), c_ = i & 31;
                g_z[(size_t)b_ * 1536 + n2 * 32 + c_] = cur[b_ * 32 + c_];
            }
        }
    }

    // z = h2 + x1 (own rows)
    for (int i = tid; i < 128 * 32; i += 256) {
        const int b_ = crank * 128 + (i >> 5), c_ = i & 31;
        const size_t idx = (size_t)b_ * 1536 + n2 * 32 + c_;
        g_z[idx] = g_z[idx] + cur[b_ * 32 + c_];
    }
}

// hidden = relu(Z @ W1^T + b1) ; Z:(256,1536), W1:(1000,1536)
__global__ void __launch_bounds__(256)
fc1_kernel(const float* __restrict__ w1, const float* __restrict__ b1)
{
    __shared__ float As[32][33];
    __shared__ float Bs[32][33];
    const int bm = blockIdx.x * 32;
    const int bn = blockIdx.y * 32;
    const int tid = threadIdx.x;
    const int tr = tid >> 5;
    const int tc = tid & 31;
    float acc[4] = {0.f, 0.f, 0.f, 0.f};
    for (int k0 = 0; k0 < 1536; k0 += 32) {
#pragma unroll
        for (int i = 0; i < 4; i++) {
            int r = tr * 4 + i;
            As[r][tc] = g_z[(size_t)(bm + r) * 1536 + k0 + tc];
            int nidx = bn + r;
            Bs[r][tc] = (nidx < 1000) ? w1[(size_t)nidx * 1536 + k0 + tc] : 0.f;
        }
        __syncthreads();
#pragma unroll
        for (int k = 0; k < 32; k++) {
            float bv = Bs[tc][k];
#pragma unroll
            for (int i = 0; i < 4; i++) acc[i] = fmaf(As[tr * 4 + i][k], bv, acc[i]);
        }
        __syncthreads();
    }
    const int nidx = bn + tc;
    if (nidx < 1000) {
        float bb = b1[nidx];
#pragma unroll
        for (int i = 0; i < 4; i++)
            g_h[(size_t)(bm + tr * 4 + i) * 1000 + nidx] = fmaxf(acc[i] + bb, 0.f);
    }
}

// out = hidden @ W2^T + b2 ; W2:(48,1000)
__global__ void __launch_bounds__(256)
fc2_kernel(const float* __restrict__ w2, const float* __restrict__ b2,
           float* __restrict__ out)
{
    __shared__ float sh[1000];
    const int nb = blockIdx.x;
    const int tid = threadIdx.x;
    for (int i = tid; i < 1000; i += 256) sh[i] = g_h[(size_t)nb * 1000 + i];
    __syncthreads();
    const int wid = tid >> 5, lane = tid & 31;
    for (int j = wid; j < 48; j += 8) {
        const float* wr = w2 + j * 1000;
        float acc = 0.f;
        for (int k = lane; k < 1000; k += 32) acc = fmaf(sh[k], wr[k], acc);
#pragma unroll
        for (int off = 16; off; off >>= 1) acc += __shfl_xor_sync(0xffffffffu, acc, off);
        if (lane == 0) out[nb * 48 + j] = acc + b2[j];
    }
}

extern "C" void kernel_launch(void* const* d_in, const int* in_sizes, int n_in,
                              void* d_out, int out_size)
{
    const float* x    = (const float*)d_in[0];
    const float* Wih0 = (const float*)d_in[1];
    const float* Wih1 = (const float*)d_in[2];
    const float* Whh1 = (const float*)d_in[3];
    const float* bih1 = (const float*)d_in[4];
    const float* bhh1 = (const float*)d_in[5];
    const float* Wih2 = (const float*)d_in[6];
    const float* Whh2 = (const float*)d_in[7];
    const float* bih2 = (const float*)d_in[8];
    const float* bhh2 = (const float*)d_in[9];
    const float* w1   = (const float*)d_in[10];
    const float* b1   = (const float*)d_in[11];
    const float* w2   = (const float*)d_in[12];
    const float* b2   = (const float*)d_in[13];
    float* out = (float*)d_out;

    // 20736 + 8192 + 8192 + 4096 + 8704 + 64 = 49,984 floats = 199,936 B
    const size_t smem = (size_t)(2 * XGW * 64 + 2 * TSEQ * 32 + 4096 + 2 * 128 * WIHP + 64) * sizeof(float);
    cudaFuncSetAttribute(lstm_kernel, cudaFuncAttributeMaxDynamicSharedMemorySize, (int)smem);

    lstm_kernel<<<2 * NSEQ, 256, smem>>>(x, Wih0, Wih1, Whh1, bih1, bhh1,
                                         Wih2, Whh2, bih2, bhh2);
    fc1_kernel<<<dim3(8, 32), 256>>>(w1, b1);
    fc2_kernel<<<TSEQ, 256>>>(w2, b2, out);
}